// round 4
// baseline (speedup 1.0000x reference)
#include <cuda_runtime.h>
#include <math.h>

// Problem constants
#define NDIM    256
#define NCODE   2048
#define DECAYF  0.99f
#define ONE_MINUS_DECAY (1.0f - 0.99f)
#define EPSF    1e-5f
#define NORM_EPSF 1e-12f

// GEMM tiling
#define BM 128
#define BN 128
#define BK 8

// ---------------- scratch (device globals; no allocation) ----------------
__device__ float g_cn[NCODE * NDIM];     // normalized codebook
__device__ float g_sum[NCODE * NDIM];    // scatter embed_sum
__device__ float g_counts[NCODE];        // scatter counts
__device__ float g_total;                // sum of new_cluster_size

// ---------------- kernel 0: zero scratch accumulators ----------------
__global__ void kzero() {
    int i = blockIdx.x * 256 + threadIdx.x;
    if (i < NCODE * NDIM) g_sum[i] = 0.0f;
    if (i < NCODE) g_counts[i] = 0.0f;
}

// ---------------- kernel 1: normalize codebook rows ----------------
__global__ void knorm(const float* __restrict__ embed) {
    int c = blockIdx.x;
    int d = threadIdx.x;              // 256 threads, 1 elem each
    float v = embed[c * NDIM + d];
    float s = v * v;
    __shared__ float red[8];
    #pragma unroll
    for (int o = 16; o > 0; o >>= 1) s += __shfl_xor_sync(0xffffffffu, s, o);
    if ((d & 31) == 0) red[d >> 5] = s;
    __syncthreads();
    if (d < 8) {
        float t = red[d];
        #pragma unroll
        for (int o = 4; o > 0; o >>= 1) t += __shfl_xor_sync(0xffu, t, o);
        if (d == 0) red[0] = t;
    }
    __syncthreads();
    float n = fmaxf(sqrtf(red[0]), NORM_EPSF);
    g_cn[c * NDIM + d] = v / n;
}

// ---------------- kernel 2: fused scores GEMM + argmax + gather/scatter ----
// Static SMEM: sm sized for max(GEMM buffers 4096, argmax scratch 4352) floats.
__global__ void __launch_bounds__(256, 1)
kmain(const float* __restrict__ X, const float* __restrict__ embed,
      float* __restrict__ outq, float* __restrict__ outind) {
    __shared__ float sm[BM * 17 * 2];        // 4352 floats = 17 KB
    __shared__ int sidx[BM];
    float* As = sm;                          // [2][BK][BM]   (uses 2048)
    float* Bs = sm + 2 * BK * BM;            // [2][BK][BN]   (uses 2048)
    float* rv = sm;                          // alias: [BM][17]  (2176)
    int*   ri = (int*)(sm + BM * 17);        // alias: [BM][17]  (2176)

    const int t  = threadIdx.x;
    const int tx = t & 15;                   // code group (8 codes)
    const int ty = t >> 4;                   // row group (8 rows)
    const size_t row0 = (size_t)blockIdx.x * BM;
    const float4* X4 = (const float4*)(X + row0 * NDIM);   // [128][64]

    const int lr = t >> 1;                   // staging row 0..127
    const int lc = t & 1;                    // staging f4 col within 8-wide chunk

    float bestv[8];
    int   besti[8];
    #pragma unroll
    for (int i = 0; i < 8; i++) { bestv[i] = -3e38f; besti[i] = 0; }

    for (int ct = 0; ct < NCODE / BN; ct++) {
        const float4* Bg4 = (const float4*)(g_cn + (size_t)ct * BN * NDIM);

        __syncthreads();   // previous tile's compute done before restaging buf 0
        // stage chunk 0 into buffer 0
        {
            float4 a = X4[lr * 64 + lc];
            float4 b = Bg4[lr * 64 + lc];
            int d0 = lc * 4;
            As[(d0 + 0) * BM + lr] = a.x;
            As[(d0 + 1) * BM + lr] = a.y;
            As[(d0 + 2) * BM + lr] = a.z;
            As[(d0 + 3) * BM + lr] = a.w;
            Bs[(d0 + 0) * BN + lr] = b.x;
            Bs[(d0 + 1) * BN + lr] = b.y;
            Bs[(d0 + 2) * BN + lr] = b.z;
            Bs[(d0 + 3) * BN + lr] = b.w;
        }
        __syncthreads();

        float acc[8][8];
        #pragma unroll
        for (int i = 0; i < 8; i++)
            #pragma unroll
            for (int j = 0; j < 8; j++) acc[i][j] = 0.0f;

        #pragma unroll 1
        for (int kt = 0; kt < NDIM / BK; kt++) {
            float4 na, nb;
            const bool more = (kt + 1 < NDIM / BK);
            if (more) {
                int col = (kt + 1) * 2 + lc;
                na = X4[lr * 64 + col];
                nb = Bg4[lr * 64 + col];
            }

            const float* Ac = As + (kt & 1) * BK * BM;
            const float* Bc = Bs + (kt & 1) * BK * BN;
            #pragma unroll
            for (int kk = 0; kk < BK; kk++) {
                float a[8], b[8];
                *(float4*)(&a[0]) = *(const float4*)(Ac + kk * BM + ty * 8);
                *(float4*)(&a[4]) = *(const float4*)(Ac + kk * BM + ty * 8 + 4);
                *(float4*)(&b[0]) = *(const float4*)(Bc + kk * BN + tx * 8);
                *(float4*)(&b[4]) = *(const float4*)(Bc + kk * BN + tx * 8 + 4);
                #pragma unroll
                for (int i = 0; i < 8; i++)
                    #pragma unroll
                    for (int j = 0; j < 8; j++)
                        acc[i][j] = fmaf(a[i], b[j], acc[i][j]);
            }

            if (more) {
                __syncthreads();
                float* An = As + ((kt + 1) & 1) * BK * BM;
                float* Bn = Bs + ((kt + 1) & 1) * BK * BN;
                int d0 = lc * 4;
                An[(d0 + 0) * BM + lr] = na.x;
                An[(d0 + 1) * BM + lr] = na.y;
                An[(d0 + 2) * BM + lr] = na.z;
                An[(d0 + 3) * BM + lr] = na.w;
                Bn[(d0 + 0) * BN + lr] = nb.x;
                Bn[(d0 + 1) * BN + lr] = nb.y;
                Bn[(d0 + 2) * BN + lr] = nb.z;
                Bn[(d0 + 3) * BN + lr] = nb.w;
                __syncthreads();
            }
        }

        // running argmax (ascending code order -> first-max semantics)
        #pragma unroll
        for (int i = 0; i < 8; i++) {
            #pragma unroll
            for (int j = 0; j < 8; j++) {
                float v = acc[i][j];
                if (v > bestv[i]) { bestv[i] = v; besti[i] = ct * BN + tx * 8 + j; }
            }
        }
    }

    // ---- cross-thread argmax reduction (tie -> smaller index) ----
    __syncthreads();   // GEMM buffers dead; safe to alias with rv/ri
    #pragma unroll
    for (int i = 0; i < 8; i++) {
        rv[(ty * 8 + i) * 17 + tx] = bestv[i];
        ri[(ty * 8 + i) * 17 + tx] = besti[i];
    }
    __syncthreads();
    if (t < BM) {
        float bv = rv[t * 17]; int bi = ri[t * 17];
        #pragma unroll
        for (int k = 1; k < 16; k++) {
            float v = rv[t * 17 + k]; int ix = ri[t * 17 + k];
            if (v > bv || (v == bv && ix < bi)) { bv = v; bi = ix; }
        }
        sidx[t] = bi;
        outind[row0 + t] = (float)bi;
        atomicAdd(&g_counts[bi], 1.0f);
    }
    __syncthreads();

    // ---- gather quantized = embed[idx] ----
    {
        const float4* E4 = (const float4*)embed;
        float4* Q4 = (float4*)(outq + row0 * NDIM);
        #pragma unroll
        for (int i = 0; i < 32; i++) {
            int e  = t + i * 256;
            int r  = e >> 6;
            int c4 = e & 63;
            Q4[r * 64 + c4] = E4[(size_t)sidx[r] * 64 + c4];
        }
    }

    // ---- scatter embed_sum += x rows (coalesced fp32 REDG) ----
    {
        const float* Xg = X + row0 * NDIM;
        #pragma unroll 4
        for (int i = 0; i < 128; i++) {        // row i, dim t
            atomicAdd(&g_sum[(size_t)sidx[i] * NDIM + t], Xg[i * NDIM + t]);
        }
    }
}

// ---------------- kernel 3: new_cluster_size + total ----------------
__global__ void kema1(const float* __restrict__ cs, float* __restrict__ out_ncs) {
    int t = threadIdx.x;                  // 1024
    __shared__ float red[32];
    float s = 0.0f;
    for (int c = t; c < NCODE; c += 1024) {
        float v = cs[c] * DECAYF + g_counts[c] * ONE_MINUS_DECAY;
        out_ncs[c] = v;
        s += v;
    }
    #pragma unroll
    for (int o = 16; o > 0; o >>= 1) s += __shfl_xor_sync(0xffffffffu, s, o);
    if ((t & 31) == 0) red[t >> 5] = s;
    __syncthreads();
    if (t < 32) {
        float v = red[t];
        #pragma unroll
        for (int o = 16; o > 0; o >>= 1) v += __shfl_xor_sync(0xffffffffu, v, o);
        if (t == 0) g_total = v;
    }
}

// ---------------- kernel 4: new_embed_avg + new_embed ----------------
__global__ void kema2(const float* __restrict__ cs, const float* __restrict__ avg,
                      float* __restrict__ out_embed, float* __restrict__ out_avg) {
    int c = blockIdx.x;
    int d = threadIdx.x;                  // 256
    float ncs = cs[c] * DECAYF + g_counts[c] * ONE_MINUS_DECAY;
    float total = g_total;
    float cssm = (ncs + EPSF) / (total + (float)NCODE * EPSF) * total;
    float na = avg[c * NDIM + d] * DECAYF + g_sum[c * NDIM + d] * ONE_MINUS_DECAY;
    out_avg[c * NDIM + d] = na;
    float v = na / cssm;
    float s = v * v;
    __shared__ float red[8];
    #pragma unroll
    for (int o = 16; o > 0; o >>= 1) s += __shfl_xor_sync(0xffffffffu, s, o);
    if ((d & 31) == 0) red[d >> 5] = s;
    __syncthreads();
    if (d < 8) {
        float tv = red[d];
        #pragma unroll
        for (int o = 4; o > 0; o >>= 1) tv += __shfl_xor_sync(0xffu, tv, o);
        if (d == 0) red[0] = tv;
    }
    __syncthreads();
    float n = fmaxf(sqrtf(red[0]), NORM_EPSF);
    out_embed[c * NDIM + d] = v / n;
}

// ---------------- launch: kernel launches ONLY ----------------
extern "C" void kernel_launch(void* const* d_in, const int* in_sizes, int n_in,
                              void* d_out, int out_size) {
    const float* x     = (const float*)d_in[0];   // [N, 256]
    const float* embed = (const float*)d_in[1];   // [2048, 256]
    const float* cs    = (const float*)d_in[2];   // [2048]
    const float* avg   = (const float*)d_in[3];   // [2048, 256]

    const int N = in_sizes[0] / NDIM;             // 65536

    float* out      = (float*)d_out;
    float* outq     = out;                                 // N*256
    float* outind   = outq + (size_t)N * NDIM;             // N
    float* outembed = outind + N;                          // 2048*256
    float* outncs   = outembed + (size_t)NCODE * NDIM;     // 2048
    float* outavg   = outncs + NCODE;                      // 2048*256

    kzero<<<(NCODE * NDIM + 255) / 256, 256>>>();
    knorm<<<NCODE, 256>>>(embed);
    kmain<<<N / BM, 256>>>(x, embed, outq, outind);
    kema1<<<1, 1024>>>(cs, outncs);
    kema2<<<NCODE, 256>>>(cs, avg, outembed, outavg);
}

// round 7
// speedup vs baseline: 1.4009x; 1.4009x over previous
#include <cuda_runtime.h>
#include <cuda_bf16.h>
#include <math.h>
#include <stdint.h>

#define NDIM    256
#define NCODE   2048
#define DECAYF  0.99f
#define ONE_MINUS_DECAY (1.0f - 0.99f)
#define EPSF    1e-5f
#define NORM_EPSF 1e-12f
#define NROWS   65536
#define MARGIN  4e-3f

// ---------------- device scratch (no allocation) ----------------
__device__ float g_cnT[NDIM * NCODE];           // transposed normalized codebook
__device__ __nv_bfloat16 g_ch[NCODE * NDIM];    // codebook hi
__device__ __nv_bfloat16 g_cl[NCODE * NDIM];    // codebook lo
__device__ __nv_bfloat16 g_xh[NROWS * NDIM];    // x hi
__device__ __nv_bfloat16 g_xl[NROWS * NDIM];    // x lo
__device__ float g_sum[NCODE * NDIM];
__device__ float g_counts[NCODE];
__device__ float g_total;
__device__ int   g_idx[NROWS];
__device__ int   g_flagrows[NROWS];
__device__ int   g_nflag;

// ---------------- helpers ----------------
__device__ __forceinline__ uint32_t smem_u32(const void* p) {
    uint32_t a;
    asm("{ .reg .u64 t; cvta.to.shared.u64 t, %1; cvt.u32.u64 %0, t; }" : "=r"(a) : "l"(p));
    return a;
}
__device__ __forceinline__ void cp16(uint32_t dst, const void* src) {
    asm volatile("cp.async.cg.shared.global [%0], [%1], 16;" :: "r"(dst), "l"(src) : "memory");
}
#define CP_COMMIT() asm volatile("cp.async.commit_group;" ::: "memory")
#define CP_WAIT0()  asm volatile("cp.async.wait_group 0;" ::: "memory")
#define CP_WAIT1()  asm volatile("cp.async.wait_group 1;" ::: "memory")

__device__ __forceinline__ void hmma16816(float* c, const unsigned* a,
                                          unsigned b0, unsigned b1) {
    asm volatile(
        "mma.sync.aligned.m16n8k16.row.col.f32.bf16.bf16.f32 "
        "{%0,%1,%2,%3}, {%4,%5,%6,%7}, {%8,%9}, {%0,%1,%2,%3};"
        : "+f"(c[0]), "+f"(c[1]), "+f"(c[2]), "+f"(c[3])
        : "r"(a[0]), "r"(a[1]), "r"(a[2]), "r"(a[3]), "r"(b0), "r"(b1));
}

// ---------------- kernel 0: zero scratch ----------------
__global__ void kzero() {
    int i = blockIdx.x * 256 + threadIdx.x;
    if (i < NCODE * NDIM) g_sum[i] = 0.0f;
    if (i < NCODE) g_counts[i] = 0.0f;
    if (i == 0) g_nflag = 0;
}

// ---------------- kernel 1: split X into hi/lo bf16 ----------------
__global__ void kprep(const float* __restrict__ X) {
    int i = blockIdx.x * 256 + threadIdx.x;     // over NROWS*NDIM/4
    float4 v = ((const float4*)X)[i];
    __nv_bfloat16 h0 = __float2bfloat16(v.x), h1 = __float2bfloat16(v.y);
    __nv_bfloat16 h2 = __float2bfloat16(v.z), h3 = __float2bfloat16(v.w);
    __nv_bfloat162* H = (__nv_bfloat162*)g_xh;
    __nv_bfloat162* L = (__nv_bfloat162*)g_xl;
    H[2 * i]     = __nv_bfloat162(h0, h1);
    H[2 * i + 1] = __nv_bfloat162(h2, h3);
    L[2 * i]     = __nv_bfloat162(__float2bfloat16(v.x - __bfloat162float(h0)),
                                  __float2bfloat16(v.y - __bfloat162float(h1)));
    L[2 * i + 1] = __nv_bfloat162(__float2bfloat16(v.z - __bfloat162float(h2)),
                                  __float2bfloat16(v.w - __bfloat162float(h3)));
}

// ---------------- kernel 2: normalize + split codebook ----------------
__global__ void knorm(const float* __restrict__ embed) {
    int c = blockIdx.x, d = threadIdx.x;
    float v = embed[c * NDIM + d];
    float s = v * v;
    __shared__ float red[8];
    #pragma unroll
    for (int o = 16; o > 0; o >>= 1) s += __shfl_xor_sync(0xffffffffu, s, o);
    if ((d & 31) == 0) red[d >> 5] = s;
    __syncthreads();
    if (d < 8) {
        float t = red[d];
        #pragma unroll
        for (int o = 4; o > 0; o >>= 1) t += __shfl_xor_sync(0xffu, t, o);
        if (d == 0) red[0] = t;
    }
    __syncthreads();
    float n = fmaxf(sqrtf(red[0]), NORM_EPSF);
    float vn = v / n;
    g_cnT[d * NCODE + c] = vn;
    __nv_bfloat16 h = __float2bfloat16(vn);
    g_ch[c * NDIM + d] = h;
    g_cl[c * NDIM + d] = __float2bfloat16(vn - __bfloat162float(h));
}

// ---------------- kernel 3: HMMA scores + top-2 argmax ----------------
// 256 threads = 8 warps; warp w owns rows [w*16, w*16+16).
// k-chunks of 16 dims, double-buffered cp.async. Static SMEM 40KB.
__global__ void __launch_bounds__(256, 1)
kmain() {
    __shared__ __align__(16) __nv_bfloat16 sAh[2][128 * 16];  // 8 KB
    __shared__ __align__(16) __nv_bfloat16 sAl[2][128 * 16];  // 8 KB
    __shared__ __align__(16) __nv_bfloat16 sBh[2][128 * 24];  // 12 KB (48B rows)
    __shared__ __align__(16) __nv_bfloat16 sBl[2][128 * 24];  // 12 KB

    const int tid  = threadIdx.x;
    const int w    = tid >> 5;
    const int lane = tid & 31;
    const int r    = lane >> 2;
    const int t    = lane & 3;
    const size_t row0 = (size_t)blockIdx.x * 128;

    // staging assignment: thread -> (row sr, 8-elem half sh) of each piece
    const int sr = tid >> 1, sh = tid & 1;
    const size_t aoff = (row0 + sr) * NDIM + sh * 8;
    const uint32_t dAh[2] = { smem_u32(&sAh[0][sr * 16 + sh * 8]), smem_u32(&sAh[1][sr * 16 + sh * 8]) };
    const uint32_t dAl[2] = { smem_u32(&sAl[0][sr * 16 + sh * 8]), smem_u32(&sAl[1][sr * 16 + sh * 8]) };
    const uint32_t dBh[2] = { smem_u32(&sBh[0][sr * 24 + sh * 8]), smem_u32(&sBh[1][sr * 24 + sh * 8]) };
    const uint32_t dBl[2] = { smem_u32(&sBl[0][sr * 24 + sh * 8]), smem_u32(&sBl[1][sr * 24 + sh * 8]) };

    auto stage = [&](int tile, int kc, int b) {
        size_t ka = aoff + kc * 16;
        size_t kb = (size_t)(tile * 128 + sr) * NDIM + kc * 16 + sh * 8;
        cp16(dAh[b], g_xh + ka);
        cp16(dAl[b], g_xl + ka);
        cp16(dBh[b], g_ch + kb);
        cp16(dBl[b], g_cl + kb);
    };

    // per-thread running top-2 for its two rows (wr and wr+8)
    float bA1 = -3e38f, bA2 = -3e38f, bB1 = -3e38f, bB2 = -3e38f;
    int iA = 0, iB = 0;

    stage(0, 0, 0);
    CP_COMMIT();

    const int abase = (w * 16 + r) * 16 + 2 * t;   // A frag base (elems)

    for (int ct = 0; ct < 16; ct++) {
        float acc[16][4];
        #pragma unroll
        for (int f = 0; f < 16; f++) {
            acc[f][0] = 0.0f; acc[f][1] = 0.0f; acc[f][2] = 0.0f; acc[f][3] = 0.0f;
        }

        #pragma unroll 1
        for (int kc = 0; kc < 16; kc++) {
            int g = ct * 16 + kc;
            int b = g & 1;
            bool more = (g + 1 < 256);
            if (more) {
                int ng = g + 1;
                stage(ng >> 4, ng & 15, ng & 1);
                CP_COMMIT();
                CP_WAIT1();
            } else {
                CP_WAIT0();
            }
            __syncthreads();

            unsigned ah[4], al[4];
            ah[0] = *(const unsigned*)&sAh[b][abase];
            ah[1] = *(const unsigned*)&sAh[b][abase + 128];
            ah[2] = *(const unsigned*)&sAh[b][abase + 8];
            ah[3] = *(const unsigned*)&sAh[b][abase + 136];
            al[0] = *(const unsigned*)&sAl[b][abase];
            al[1] = *(const unsigned*)&sAl[b][abase + 128];
            al[2] = *(const unsigned*)&sAl[b][abase + 8];
            al[3] = *(const unsigned*)&sAl[b][abase + 136];

            #pragma unroll
            for (int f = 0; f < 16; f++) {
                int bb = f * 192 + r * 24 + 2 * t;
                unsigned b0h = *(const unsigned*)&sBh[b][bb];
                unsigned b1h = *(const unsigned*)&sBh[b][bb + 8];
                unsigned b0l = *(const unsigned*)&sBl[b][bb];
                unsigned b1l = *(const unsigned*)&sBl[b][bb + 8];
                hmma16816(acc[f], ah, b0h, b1h);   // Xh*Ch
                hmma16816(acc[f], al, b0h, b1h);   // Xl*Ch
                hmma16816(acc[f], ah, b0l, b1l);   // Xh*Cl
            }
            __syncthreads();
        }

        // fold tile scores into running top-2
        #pragma unroll
        for (int f = 0; f < 16; f++) {
            int cb = ct * 128 + f * 8 + 2 * t;
            float v;
            v = acc[f][0]; if (v > bA1) { bA2 = bA1; bA1 = v; iA = cb; }     else if (v > bA2) bA2 = v;
            v = acc[f][1]; if (v > bA1) { bA2 = bA1; bA1 = v; iA = cb + 1; } else if (v > bA2) bA2 = v;
            v = acc[f][2]; if (v > bB1) { bB2 = bB1; bB1 = v; iB = cb; }     else if (v > bB2) bB2 = v;
            v = acc[f][3]; if (v > bB1) { bB2 = bB1; bB1 = v; iB = cb + 1; } else if (v > bB2) bB2 = v;
        }
    }

    // cross-lane merge within quad (lanes 4r..4r+3 share rows)
    #pragma unroll
    for (int o = 1; o <= 2; o <<= 1) {
        float o1 = __shfl_xor_sync(0xffffffffu, bA1, o);
        float o2 = __shfl_xor_sync(0xffffffffu, bA2, o);
        int   oi = __shfl_xor_sync(0xffffffffu, iA, o);
        if (o1 > bA1 || (o1 == bA1 && oi < iA)) { bA2 = fmaxf(bA1, o2); bA1 = o1; iA = oi; }
        else bA2 = fmaxf(bA2, o1);
        o1 = __shfl_xor_sync(0xffffffffu, bB1, o);
        o2 = __shfl_xor_sync(0xffffffffu, bB2, o);
        oi = __shfl_xor_sync(0xffffffffu, iB, o);
        if (o1 > bB1 || (o1 == bB1 && oi < iB)) { bB2 = fmaxf(bB1, o2); bB1 = o1; iB = oi; }
        else bB2 = fmaxf(bB2, o1);
    }

    if (t == 0) {
        size_t rowA = row0 + w * 16 + r;
        size_t rowB = rowA + 8;
        g_idx[rowA] = iA;
        g_idx[rowB] = iB;
        if (bA1 - bA2 < MARGIN) { int p = atomicAdd(&g_nflag, 1); g_flagrows[p] = (int)rowA; }
        if (bB1 - bB2 < MARGIN) { int p = atomicAdd(&g_nflag, 1); g_flagrows[p] = (int)rowB; }
    }
}

// ---------------- kernel 4: exact fp32 recheck of flagged rows ----------------
__global__ void __launch_bounds__(256, 4)
krecheck(const float* __restrict__ X) {
    __shared__ float xs[8 * NDIM];
    __shared__ int rows[8];
    __shared__ float sv[8 * 256];
    __shared__ int si[8 * 256];
    const int tid = threadIdx.x;
    int nf = g_nflag;

    for (int g = blockIdx.x; g * 8 < nf; g += gridDim.x) {
        int cnt = min(8, nf - g * 8);
        if (tid < 8) rows[tid] = (tid < cnt) ? g_flagrows[g * 8 + tid] : -1;
        __syncthreads();
        for (int i = tid; i < 8 * NDIM; i += 256)
            xs[i] = (i >> 8) < cnt ? X[(size_t)rows[i >> 8] * NDIM + (i & 255)] : 0.0f;
        __syncthreads();

        float bv[8]; int bix[8];
        #pragma unroll
        for (int r = 0; r < 8; r++) { bv[r] = -3e38f; bix[r] = 0; }
        for (int chk = 0; chk < 8; chk++) {
            int code = chk * 256 + tid;
            float a[8];
            #pragma unroll
            for (int r = 0; r < 8; r++) a[r] = 0.0f;
            for (int k = 0; k < NDIM; k++) {
                float bb = g_cnT[k * NCODE + code];
                #pragma unroll
                for (int r = 0; r < 8; r++) a[r] = fmaf(xs[r * NDIM + k], bb, a[r]);
            }
            #pragma unroll
            for (int r = 0; r < 8; r++)
                if (a[r] > bv[r]) { bv[r] = a[r]; bix[r] = code; }
        }
        #pragma unroll
        for (int r = 0; r < 8; r++) { sv[r * 256 + tid] = bv[r]; si[r * 256 + tid] = bix[r]; }
        __syncthreads();
        int w = tid >> 5, l = tid & 31;
        if (w < 8 && rows[w] >= 0) {
            float v = -3e38f; int ix = 0;
            #pragma unroll
            for (int j = 0; j < 8; j++) {
                float vv = sv[w * 256 + l + j * 32]; int ii = si[w * 256 + l + j * 32];
                if (vv > v || (vv == v && ii < ix)) { v = vv; ix = ii; }
            }
            #pragma unroll
            for (int o = 16; o > 0; o >>= 1) {
                float ov = __shfl_xor_sync(0xffffffffu, v, o);
                int oi = __shfl_xor_sync(0xffffffffu, ix, o);
                if (ov > v || (ov == v && oi < ix)) { v = ov; ix = oi; }
            }
            if (l == 0) g_idx[rows[w]] = ix;
        }
        __syncthreads();
    }
}

// ---------------- kernel 5: gather/scatter/outputs ----------------
__global__ void __launch_bounds__(256, 1)
kfinal(const float* __restrict__ X, const float* __restrict__ embed,
       float* __restrict__ outq, float* __restrict__ outind) {
    __shared__ int sidx[128];
    const int t = threadIdx.x;
    const size_t row0 = (size_t)blockIdx.x * 128;
    if (t < 128) {
        int bi = g_idx[row0 + t];
        sidx[t] = bi;
        outind[row0 + t] = (float)bi;
        atomicAdd(&g_counts[bi], 1.0f);
    }
    __syncthreads();
    {
        const float4* E4 = (const float4*)embed;
        float4* Q4 = (float4*)(outq + row0 * NDIM);
        #pragma unroll
        for (int i = 0; i < 32; i++) {
            int e = t + i * 256;
            int r = e >> 6, c4 = e & 63;
            Q4[r * 64 + c4] = E4[(size_t)sidx[r] * 64 + c4];
        }
    }
    {
        const float* Xg = X + row0 * NDIM;
        #pragma unroll 4
        for (int i = 0; i < 128; i++)
            atomicAdd(&g_sum[(size_t)sidx[i] * NDIM + t], Xg[i * NDIM + t]);
    }
}

// ---------------- kernels 6/7: EMA epilogue ----------------
__global__ void kema1(const float* __restrict__ cs, float* __restrict__ out_ncs) {
    int t = threadIdx.x;
    __shared__ float red[32];
    float s = 0.0f;
    for (int c = t; c < NCODE; c += 1024) {
        float v = cs[c] * DECAYF + g_counts[c] * ONE_MINUS_DECAY;
        out_ncs[c] = v;
        s += v;
    }
    #pragma unroll
    for (int o = 16; o > 0; o >>= 1) s += __shfl_xor_sync(0xffffffffu, s, o);
    if ((t & 31) == 0) red[t >> 5] = s;
    __syncthreads();
    if (t < 32) {
        float v = red[t];
        #pragma unroll
        for (int o = 16; o > 0; o >>= 1) v += __shfl_xor_sync(0xffffffffu, v, o);
        if (t == 0) g_total = v;
    }
}
__global__ void kema2(const float* __restrict__ cs, const float* __restrict__ avg,
                      float* __restrict__ out_embed, float* __restrict__ out_avg) {
    int c = blockIdx.x, d = threadIdx.x;
    float ncs = cs[c] * DECAYF + g_counts[c] * ONE_MINUS_DECAY;
    float total = g_total;
    float cssm = (ncs + EPSF) / (total + (float)NCODE * EPSF) * total;
    float na = avg[c * NDIM + d] * DECAYF + g_sum[c * NDIM + d] * ONE_MINUS_DECAY;
    out_avg[c * NDIM + d] = na;
    float v = na / cssm;
    float s = v * v;
    __shared__ float red[8];
    #pragma unroll
    for (int o = 16; o > 0; o >>= 1) s += __shfl_xor_sync(0xffffffffu, s, o);
    if ((d & 31) == 0) red[d >> 5] = s;
    __syncthreads();
    if (d < 8) {
        float tv = red[d];
        #pragma unroll
        for (int o = 4; o > 0; o >>= 1) tv += __shfl_xor_sync(0xffu, tv, o);
        if (d == 0) red[0] = tv;
    }
    __syncthreads();
    float n = fmaxf(sqrtf(red[0]), NORM_EPSF);
    out_embed[c * NDIM + d] = v / n;
}

// ---------------- launch: kernel launches ONLY ----------------
extern "C" void kernel_launch(void* const* d_in, const int* in_sizes, int n_in,
                              void* d_out, int out_size) {
    const float* x     = (const float*)d_in[0];
    const float* embed = (const float*)d_in[1];
    const float* cs    = (const float*)d_in[2];
    const float* avg   = (const float*)d_in[3];
    const int N = in_sizes[0] / NDIM;

    float* out      = (float*)d_out;
    float* outq     = out;
    float* outind   = outq + (size_t)N * NDIM;
    float* outembed = outind + N;
    float* outncs   = outembed + (size_t)NCODE * NDIM;
    float* outavg   = outncs + NCODE;

    kzero<<<(NCODE * NDIM + 255) / 256, 256>>>();
    kprep<<<(N * NDIM / 4 + 255) / 256, 256>>>(x);
    knorm<<<NCODE, 256>>>(embed);
    kmain<<<N / 128, 256>>>();
    krecheck<<<256, 256>>>(x);
    kfinal<<<N / 128, 256>>>(x, embed, outq, outind);
    kema1<<<1, 1024>>>(cs, outncs);
    kema2<<<NCODE, 256>>>(cs, avg, outembed, outavg);
}

// round 8
// speedup vs baseline: 1.4134x; 1.0089x over previous
#include <cuda_runtime.h>
#include <cuda_bf16.h>
#include <math.h>
#include <stdint.h>

#define NDIM    256
#define NCODE   2048
#define DECAYF  0.99f
#define ONE_MINUS_DECAY (1.0f - 0.99f)
#define EPSF    1e-5f
#define NORM_EPSF 1e-12f
#define NROWS   65536
#define MARGIN  4e-3f

// ---------------- device scratch (no allocation) ----------------
__device__ float g_cnT[NDIM * NCODE];           // transposed normalized codebook
__device__ __nv_bfloat16 g_ch[NCODE * NDIM];    // codebook hi
__device__ __nv_bfloat16 g_cl[NCODE * NDIM];    // codebook lo
__device__ __nv_bfloat16 g_xh[NROWS * NDIM];    // x hi
__device__ __nv_bfloat16 g_xl[NROWS * NDIM];    // x lo
__device__ float g_sum[NCODE * NDIM];
__device__ float g_counts[NCODE];
__device__ float g_total;
__device__ int   g_idx[NROWS];
__device__ int   g_flagrows[NROWS];
__device__ int   g_nflag;

// ---------------- helpers ----------------
__device__ __forceinline__ uint32_t smem_u32(const void* p) {
    uint32_t a;
    asm("{ .reg .u64 t; cvta.to.shared.u64 t, %1; cvt.u32.u64 %0, t; }" : "=r"(a) : "l"(p));
    return a;
}
__device__ __forceinline__ void cp16(uint32_t dst, const void* src) {
    asm volatile("cp.async.cg.shared.global [%0], [%1], 16;" :: "r"(dst), "l"(src) : "memory");
}
#define CP_COMMIT() asm volatile("cp.async.commit_group;" ::: "memory")
#define CP_WAIT2()  asm volatile("cp.async.wait_group 2;" ::: "memory")

__device__ __forceinline__ void hmma16816(float* c, const unsigned* a,
                                          unsigned b0, unsigned b1) {
    asm volatile(
        "mma.sync.aligned.m16n8k16.row.col.f32.bf16.bf16.f32 "
        "{%0,%1,%2,%3}, {%4,%5,%6,%7}, {%8,%9}, {%0,%1,%2,%3};"
        : "+f"(c[0]), "+f"(c[1]), "+f"(c[2]), "+f"(c[3])
        : "r"(a[0]), "r"(a[1]), "r"(a[2]), "r"(a[3]), "r"(b0), "r"(b1));
}
__device__ __forceinline__ void ldsm_x4(unsigned& r0, unsigned& r1,
                                        unsigned& r2, unsigned& r3, uint32_t addr) {
    asm volatile("ldmatrix.sync.aligned.m8n8.x4.shared.b16 {%0,%1,%2,%3}, [%4];"
                 : "=r"(r0), "=r"(r1), "=r"(r2), "=r"(r3) : "r"(addr));
}

// ---------------- kernel 0: zero scratch ----------------
__global__ void kzero() {
    int i = blockIdx.x * 256 + threadIdx.x;
    if (i < NCODE * NDIM) g_sum[i] = 0.0f;
    if (i < NCODE) g_counts[i] = 0.0f;
    if (i == 0) g_nflag = 0;
}

// ---------------- kernel 1: split X into hi/lo bf16 ----------------
__global__ void kprep(const float* __restrict__ X) {
    int i = blockIdx.x * 256 + threadIdx.x;     // over NROWS*NDIM/4
    float4 v = ((const float4*)X)[i];
    __nv_bfloat16 h0 = __float2bfloat16(v.x), h1 = __float2bfloat16(v.y);
    __nv_bfloat16 h2 = __float2bfloat16(v.z), h3 = __float2bfloat16(v.w);
    __nv_bfloat162* H = (__nv_bfloat162*)g_xh;
    __nv_bfloat162* L = (__nv_bfloat162*)g_xl;
    H[2 * i]     = __nv_bfloat162(h0, h1);
    H[2 * i + 1] = __nv_bfloat162(h2, h3);
    L[2 * i]     = __nv_bfloat162(__float2bfloat16(v.x - __bfloat162float(h0)),
                                  __float2bfloat16(v.y - __bfloat162float(h1)));
    L[2 * i + 1] = __nv_bfloat162(__float2bfloat16(v.z - __bfloat162float(h2)),
                                  __float2bfloat16(v.w - __bfloat162float(h3)));
}

// ---------------- kernel 2: normalize + split codebook ----------------
__global__ void knorm(const float* __restrict__ embed) {
    int c = blockIdx.x, d = threadIdx.x;
    float v = embed[c * NDIM + d];
    float s = v * v;
    __shared__ float red[8];
    #pragma unroll
    for (int o = 16; o > 0; o >>= 1) s += __shfl_xor_sync(0xffffffffu, s, o);
    if ((d & 31) == 0) red[d >> 5] = s;
    __syncthreads();
    if (d < 8) {
        float t = red[d];
        #pragma unroll
        for (int o = 4; o > 0; o >>= 1) t += __shfl_xor_sync(0xffu, t, o);
        if (d == 0) red[0] = t;
    }
    __syncthreads();
    float n = fmaxf(sqrtf(red[0]), NORM_EPSF);
    float vn = v / n;
    g_cnT[d * NCODE + c] = vn;
    __nv_bfloat16 h = __float2bfloat16(vn);
    g_ch[c * NDIM + d] = h;
    g_cl[c * NDIM + d] = __float2bfloat16(vn - __bfloat162float(h));
}

// ---------------- kernel 3: HMMA scores + top-2 argmax ----------------
// 256 threads = 8 warps; warp w owns rows [w*16, w*16+16).
// B-only SMEM: 4-stage cp.async pipeline, 1 syncthreads per k-chunk.
// A fragments loaded directly from GMEM (L1-resident re-reads).
__global__ void __launch_bounds__(256, 2)
kmain() {
    __shared__ __align__(16) __nv_bfloat16 sBh[4][128 * 16];  // 4 x 4 KB
    __shared__ __align__(16) __nv_bfloat16 sBl[4][128 * 16];  // 4 x 4 KB

    const int tid  = threadIdx.x;
    const int w    = tid >> 5;
    const int lane = tid & 31;
    const int r    = lane >> 2;
    const int t    = lane & 3;
    const size_t row0 = (size_t)blockIdx.x * 128;

    const uint32_t sbh = smem_u32(&sBh[0][0]);
    const uint32_t sbl = smem_u32(&sBl[0][0]);

    // staging: thread -> (code = tid>>1, half = tid&1), 1 cp16 hi + 1 cp16 lo
    const int scode = tid >> 1, shalf = tid & 1;
    const uint32_t sdst = (uint32_t)(scode * 32 + shalf * 16);   // bytes in buffer

    // ldmatrix per-lane source offset (bytes) within a 16-code group
    const int lrow = (lane & 7) + ((lane >> 4) << 3);
    const int ldim = ((lane >> 3) & 1) * 8;
    const uint32_t lmoff = (uint32_t)((lrow * 16 + ldim) * 2);

    // A fragment base pointers (this warp's rows)
    const size_t arow = row0 + w * 16 + r;
    const __nv_bfloat16* paH = g_xh + arow * NDIM + 2 * t;
    const __nv_bfloat16* paL = g_xl + arow * NDIM + 2 * t;

    auto stage = [&](int g2) {
        int tile = g2 >> 4, kc2 = g2 & 15, b = g2 & 3;
        size_t src = (size_t)(tile * 128 + scode) * NDIM + kc2 * 16 + shalf * 8;
        cp16(sbh + (uint32_t)b * 4096 + sdst, g_ch + src);
        cp16(sbl + (uint32_t)b * 4096 + sdst, g_cl + src);
    };

    // per-thread running top-2 for its two rows (arow and arow+8)
    float bA1 = -3e38f, bA2 = -3e38f, bB1 = -3e38f, bB2 = -3e38f;
    int iA = 0, iB = 0;

    stage(0); CP_COMMIT();
    stage(1); CP_COMMIT();
    stage(2); CP_COMMIT();
    CP_WAIT2();
    __syncthreads();

    float acc[16][4];

    #pragma unroll 1
    for (int g = 0; g < 256; g++) {
        const int kc = g & 15;
        const int ct = g >> 4;
        const int b  = g & 3;

        // stage 3 chunks ahead (buffer was consumed at iter g-1, guarded by its sync)
        if (g + 3 < 256) stage(g + 3);
        CP_COMMIT();

        if (kc == 0) {
            #pragma unroll
            for (int f = 0; f < 16; f++) {
                acc[f][0] = 0.0f; acc[f][1] = 0.0f; acc[f][2] = 0.0f; acc[f][3] = 0.0f;
            }
        }

        // A fragments: 8 x LDG.32 (L1 hits after first tile)
        unsigned ah[4], al[4];
        {
            const __nv_bfloat16* ph = paH + kc * 16;
            const __nv_bfloat16* pl = paL + kc * 16;
            ah[0] = *(const unsigned*)(ph);
            ah[1] = *(const unsigned*)(ph + 8 * NDIM);
            ah[2] = *(const unsigned*)(ph + 8);
            ah[3] = *(const unsigned*)(ph + 8 * NDIM + 8);
            al[0] = *(const unsigned*)(pl);
            al[1] = *(const unsigned*)(pl + 8 * NDIM);
            al[2] = *(const unsigned*)(pl + 8);
            al[3] = *(const unsigned*)(pl + 8 * NDIM + 8);
        }

        // B fragments via ldmatrix.x4; 3-term MMA
        const uint32_t bh = sbh + (uint32_t)b * 4096 + lmoff;
        const uint32_t bl = sbl + (uint32_t)b * 4096 + lmoff;
        #pragma unroll
        for (int p = 0; p < 8; p++) {
            unsigned h0, h1, h2, h3, l0, l1, l2, l3;
            ldsm_x4(h0, h1, h2, h3, bh + p * 512);
            ldsm_x4(l0, l1, l2, l3, bl + p * 512);
            hmma16816(acc[2 * p],     ah, h0, h1);   // Xh*Ch
            hmma16816(acc[2 * p],     al, h0, h1);   // Xl*Ch
            hmma16816(acc[2 * p],     ah, l0, l1);   // Xh*Cl
            hmma16816(acc[2 * p + 1], ah, h2, h3);
            hmma16816(acc[2 * p + 1], al, h2, h3);
            hmma16816(acc[2 * p + 1], ah, l2, l3);
        }

        if (kc == 15) {
            // fold tile scores into running top-2 (ascending code order)
            #pragma unroll
            for (int f = 0; f < 16; f++) {
                int cb = ct * 128 + f * 8 + 2 * t;
                float v;
                v = acc[f][0]; if (v > bA1) { bA2 = bA1; bA1 = v; iA = cb; }     else if (v > bA2) bA2 = v;
                v = acc[f][1]; if (v > bA1) { bA2 = bA1; bA1 = v; iA = cb + 1; } else if (v > bA2) bA2 = v;
                v = acc[f][2]; if (v > bB1) { bB2 = bB1; bB1 = v; iB = cb; }     else if (v > bB2) bB2 = v;
                v = acc[f][3]; if (v > bB1) { bB2 = bB1; bB1 = v; iB = cb + 1; } else if (v > bB2) bB2 = v;
            }
        }

        CP_WAIT2();
        __syncthreads();
    }

    // cross-lane merge within quad (lanes 4r..4r+3 share rows)
    #pragma unroll
    for (int o = 1; o <= 2; o <<= 1) {
        float o1 = __shfl_xor_sync(0xffffffffu, bA1, o);
        float o2 = __shfl_xor_sync(0xffffffffu, bA2, o);
        int   oi = __shfl_xor_sync(0xffffffffu, iA, o);
        if (o1 > bA1 || (o1 == bA1 && oi < iA)) { bA2 = fmaxf(bA1, o2); bA1 = o1; iA = oi; }
        else bA2 = fmaxf(bA2, o1);
        o1 = __shfl_xor_sync(0xffffffffu, bB1, o);
        o2 = __shfl_xor_sync(0xffffffffu, bB2, o);
        oi = __shfl_xor_sync(0xffffffffu, iB, o);
        if (o1 > bB1 || (o1 == bB1 && oi < iB)) { bB2 = fmaxf(bB1, o2); bB1 = o1; iB = oi; }
        else bB2 = fmaxf(bB2, o1);
    }

    if (t == 0) {
        size_t rowA = arow;
        size_t rowB = arow + 8;
        g_idx[rowA] = iA;
        g_idx[rowB] = iB;
        if (bA1 - bA2 < MARGIN) { int p = atomicAdd(&g_nflag, 1); g_flagrows[p] = (int)rowA; }
        if (bB1 - bB2 < MARGIN) { int p = atomicAdd(&g_nflag, 1); g_flagrows[p] = (int)rowB; }
    }
}

// ---------------- kernel 4: exact fp32 recheck of flagged rows ----------------
__global__ void __launch_bounds__(256, 4)
krecheck(const float* __restrict__ X) {
    __shared__ float xs[8 * NDIM];
    __shared__ int rows[8];
    __shared__ float sv[8 * 256];
    __shared__ int si[8 * 256];
    const int tid = threadIdx.x;
    int nf = g_nflag;

    for (int g = blockIdx.x; g * 8 < nf; g += gridDim.x) {
        int cnt = min(8, nf - g * 8);
        if (tid < 8) rows[tid] = (tid < cnt) ? g_flagrows[g * 8 + tid] : -1;
        __syncthreads();
        for (int i = tid; i < 8 * NDIM; i += 256)
            xs[i] = (i >> 8) < cnt ? X[(size_t)rows[i >> 8] * NDIM + (i & 255)] : 0.0f;
        __syncthreads();

        float bv[8]; int bix[8];
        #pragma unroll
        for (int r = 0; r < 8; r++) { bv[r] = -3e38f; bix[r] = 0; }
        for (int chk = 0; chk < 8; chk++) {
            int code = chk * 256 + tid;
            float a[8];
            #pragma unroll
            for (int r = 0; r < 8; r++) a[r] = 0.0f;
            for (int k = 0; k < NDIM; k++) {
                float bb = g_cnT[k * NCODE + code];
                #pragma unroll
                for (int r = 0; r < 8; r++) a[r] = fmaf(xs[r * NDIM + k], bb, a[r]);
            }
            #pragma unroll
            for (int r = 0; r < 8; r++)
                if (a[r] > bv[r]) { bv[r] = a[r]; bix[r] = code; }
        }
        #pragma unroll
        for (int r = 0; r < 8; r++) { sv[r * 256 + tid] = bv[r]; si[r * 256 + tid] = bix[r]; }
        __syncthreads();
        int w = tid >> 5, l = tid & 31;
        if (w < 8 && rows[w] >= 0) {
            float v = -3e38f; int ix = 0;
            #pragma unroll
            for (int j = 0; j < 8; j++) {
                float vv = sv[w * 256 + l + j * 32]; int ii = si[w * 256 + l + j * 32];
                if (vv > v || (vv == v && ii < ix)) { v = vv; ix = ii; }
            }
            #pragma unroll
            for (int o = 16; o > 0; o >>= 1) {
                float ov = __shfl_xor_sync(0xffffffffu, v, o);
                int oi = __shfl_xor_sync(0xffffffffu, ix, o);
                if (ov > v || (ov == v && oi < ix)) { v = ov; ix = oi; }
            }
            if (l == 0) g_idx[rows[w]] = ix;
        }
        __syncthreads();
    }
}

// ---------------- kernel 5: gather/scatter/outputs ----------------
__global__ void __launch_bounds__(256, 1)
kfinal(const float* __restrict__ X, const float* __restrict__ embed,
       float* __restrict__ outq, float* __restrict__ outind) {
    __shared__ int sidx[128];
    const int t = threadIdx.x;
    const size_t row0 = (size_t)blockIdx.x * 128;
    if (t < 128) {
        int bi = g_idx[row0 + t];
        sidx[t] = bi;
        outind[row0 + t] = (float)bi;
        atomicAdd(&g_counts[bi], 1.0f);
    }
    __syncthreads();
    {
        const float4* E4 = (const float4*)embed;
        float4* Q4 = (float4*)(outq + row0 * NDIM);
        #pragma unroll
        for (int i = 0; i < 32; i++) {
            int e = t + i * 256;
            int r = e >> 6, c4 = e & 63;
            Q4[r * 64 + c4] = E4[(size_t)sidx[r] * 64 + c4];
        }
    }
    {
        const float* Xg = X + row0 * NDIM;
        #pragma unroll 4
        for (int i = 0; i < 128; i++)
            atomicAdd(&g_sum[(size_t)sidx[i] * NDIM + t], Xg[i * NDIM + t]);
    }
}

// ---------------- kernels 6/7: EMA epilogue ----------------
__global__ void kema1(const float* __restrict__ cs, float* __restrict__ out_ncs) {
    int t = threadIdx.x;
    __shared__ float red[32];
    float s = 0.0f;
    for (int c = t; c < NCODE; c += 1024) {
        float v = cs[c] * DECAYF + g_counts[c] * ONE_MINUS_DECAY;
        out_ncs[c] = v;
        s += v;
    }
    #pragma unroll
    for (int o = 16; o > 0; o >>= 1) s += __shfl_xor_sync(0xffffffffu, s, o);
    if ((t & 31) == 0) red[t >> 5] = s;
    __syncthreads();
    if (t < 32) {
        float v = red[t];
        #pragma unroll
        for (int o = 16; o > 0; o >>= 1) v += __shfl_xor_sync(0xffffffffu, v, o);
        if (t == 0) g_total = v;
    }
}
__global__ void kema2(const float* __restrict__ cs, const float* __restrict__ avg,
                      float* __restrict__ out_embed, float* __restrict__ out_avg) {
    int c = blockIdx.x, d = threadIdx.x;
    float ncs = cs[c] * DECAYF + g_counts[c] * ONE_MINUS_DECAY;
    float total = g_total;
    float cssm = (ncs + EPSF) / (total + (float)NCODE * EPSF) * total;
    float na = avg[c * NDIM + d] * DECAYF + g_sum[c * NDIM + d] * ONE_MINUS_DECAY;
    out_avg[c * NDIM + d] = na;
    float v = na / cssm;
    float s = v * v;
    __shared__ float red[8];
    #pragma unroll
    for (int o = 16; o > 0; o >>= 1) s += __shfl_xor_sync(0xffffffffu, s, o);
    if ((d & 31) == 0) red[d >> 5] = s;
    __syncthreads();
    if (d < 8) {
        float tv = red[d];
        #pragma unroll
        for (int o = 4; o > 0; o >>= 1) tv += __shfl_xor_sync(0xffu, tv, o);
        if (d == 0) red[0] = tv;
    }
    __syncthreads();
    float n = fmaxf(sqrtf(red[0]), NORM_EPSF);
    out_embed[c * NDIM + d] = v / n;
}

// ---------------- launch: kernel launches ONLY ----------------
extern "C" void kernel_launch(void* const* d_in, const int* in_sizes, int n_in,
                              void* d_out, int out_size) {
    const float* x     = (const float*)d_in[0];
    const float* embed = (const float*)d_in[1];
    const float* cs    = (const float*)d_in[2];
    const float* avg   = (const float*)d_in[3];
    const int N = in_sizes[0] / NDIM;

    float* out      = (float*)d_out;
    float* outq     = out;
    float* outind   = outq + (size_t)N * NDIM;
    float* outembed = outind + N;
    float* outncs   = outembed + (size_t)NCODE * NDIM;
    float* outavg   = outncs + NCODE;

    kzero<<<(NCODE * NDIM + 255) / 256, 256>>>();
    kprep<<<(N * NDIM / 4 + 255) / 256, 256>>>(x);
    knorm<<<NCODE, 256>>>(embed);
    kmain<<<N / 128, 256>>>();
    krecheck<<<256, 256>>>(x);
    kfinal<<<N / 128, 256>>>(x, embed, outq, outind);
    kema1<<<1, 1024>>>(cs, outncs);
    kema2<<<NCODE, 256>>>(cs, avg, outembed, outavg);
}